// round 2
// baseline (speedup 1.0000x reference)
#include <cuda_runtime.h>

#define NN 10000
#define EE 320000
#define DD 256
#define NDTOT (NN*DD)

// -------- scratch (static device globals; no allocation) ----------
__device__ float g_q[NDTOT];
__device__ float g_k[NDTOT];
__device__ float g_v[NDTOT];
__device__ float g_s[NDTOT];
__device__ float g_hA[NDTOT];
__device__ float g_hB[NDTOT];
__device__ float g_mean[NDTOT];
__device__ float g_z[NDTOT];
__device__ float g_logits[EE];
__device__ int   g_rowptr[NN + 1];
__device__ int   g_srcs[EE];
__device__ int   g_cnt[NN];
__device__ int   g_fill[NN];

// -------- GEMM: C[M,256] = A[M,256] @ B[256,256] (+bias / +=) ----------
__global__ void gemm_bias(const float* __restrict__ A, const float* __restrict__ B,
                          const float* __restrict__ bias, float* __restrict__ C,
                          int M, int acc_flag)
{
    __shared__ float As[16][68];   // transposed A tile, padded
    __shared__ float Bs[16][64];

    int tid = threadIdx.x;          // 256 threads
    int tx = tid & 15;              // 0..15 -> 4 output cols each
    int ty = tid >> 4;              // 0..15 -> 4 output rows each
    int bm = blockIdx.x * 64;
    int bn = blockIdx.y * 64;

    float acc[4][4];
#pragma unroll
    for (int i = 0; i < 4; i++)
#pragma unroll
        for (int j = 0; j < 4; j++) acc[i][j] = 0.f;

    int arow = tid >> 2;            // 0..63
    int ak0  = (tid & 3) * 4;       // 0,4,8,12
    int brow = tid >> 4;            // 0..15
    int bcol = (tid & 15) * 4;

    for (int kt = 0; kt < 256; kt += 16) {
        float4 av;
        if (bm + arow < M)
            av = *reinterpret_cast<const float4*>(&A[(size_t)(bm + arow) * 256 + kt + ak0]);
        else
            av = make_float4(0.f, 0.f, 0.f, 0.f);
        As[ak0 + 0][arow] = av.x;
        As[ak0 + 1][arow] = av.y;
        As[ak0 + 2][arow] = av.z;
        As[ak0 + 3][arow] = av.w;

        float4 bv = *reinterpret_cast<const float4*>(&B[(size_t)(kt + brow) * 256 + bn + bcol]);
        *reinterpret_cast<float4*>(&Bs[brow][bcol]) = bv;
        __syncthreads();

#pragma unroll
        for (int kk = 0; kk < 16; kk++) {
            float a[4], b[4];
#pragma unroll
            for (int i = 0; i < 4; i++) a[i] = As[kk][ty * 4 + i];
#pragma unroll
            for (int j = 0; j < 4; j++) b[j] = Bs[kk][tx * 4 + j];
#pragma unroll
            for (int i = 0; i < 4; i++)
#pragma unroll
                for (int j = 0; j < 4; j++)
                    acc[i][j] = fmaf(a[i], b[j], acc[i][j]);
        }
        __syncthreads();
    }

#pragma unroll
    for (int i = 0; i < 4; i++) {
        int row = bm + ty * 4 + i;
        if (row >= M) continue;
#pragma unroll
        for (int j = 0; j < 4; j++) {
            int col = bn + tx * 4 + j;
            float val = acc[i][j];
            if (acc_flag) {
                C[(size_t)row * 256 + col] += val;
            } else {
                if (bias) val += bias[col];
                C[(size_t)row * 256 + col] = val;
            }
        }
    }
}

// -------- CSR build ----------
__global__ void zero_cnt_kernel()
{
    int i = blockIdx.x * blockDim.x + threadIdx.x;
    if (i < NN) g_cnt[i] = 0;
}

__global__ void hist_kernel(const int* __restrict__ ei)
{
    int e = blockIdx.x * blockDim.x + threadIdx.x;
    if (e >= EE) return;
    int dst = ei[EE + e];
    atomicAdd(&g_cnt[dst], 1);
}

__global__ void scan_kernel()
{
    __shared__ int sh[1024];
    __shared__ int carry;
    int tid = threadIdx.x;
    if (tid == 0) { carry = 0; g_rowptr[0] = 0; }
    __syncthreads();
    for (int base = 0; base < NN; base += 1024) {
        int i = base + tid;
        int v = (i < NN) ? g_cnt[i] : 0;
        sh[tid] = v;
        __syncthreads();
        for (int off = 1; off < 1024; off <<= 1) {
            int t = (tid >= off) ? sh[tid - off] : 0;
            __syncthreads();
            sh[tid] += t;
            __syncthreads();
        }
        int incl = sh[tid] + carry;
        if (i < NN) {
            g_rowptr[i + 1] = incl;
            g_fill[i] = incl - v;   // exclusive
        }
        __syncthreads();
        if (tid == 1023) carry = incl;
        __syncthreads();
    }
}

__global__ void scatter_kernel(const int* __restrict__ ei)
{
    int e = blockIdx.x * blockDim.x + threadIdx.x;
    if (e >= EE) return;
    int src = ei[e];
    int dst = ei[EE + e];
    int pos = atomicAdd(&g_fill[dst], 1);
    g_srcs[pos] = src;
}

// -------- TransformerConv: warp per node, 2-pass softmax aggregation ----------
__global__ void attn_kernel()
{
    int gw = (blockIdx.x * blockDim.x + threadIdx.x) >> 5;
    int lane = threadIdx.x & 31;
    if (gw >= NN) return;
    int beg = g_rowptr[gw], end = g_rowptr[gw + 1];

    float qr[8];
#pragma unroll
    for (int r = 0; r < 8; r++) qr[r] = g_q[(size_t)gw * DD + r * 32 + lane];

    float m = -1e30f;
    for (int e = beg; e < end; e++) {
        int src = g_srcs[e];
        const float* kp = &g_k[(size_t)src * DD];
        float p = 0.f;
#pragma unroll
        for (int r = 0; r < 8; r++) p = fmaf(qr[r], kp[r * 32 + lane], p);
#pragma unroll
        for (int off = 16; off; off >>= 1) p += __shfl_xor_sync(0xffffffffu, p, off);
        p *= 0.0625f;                 // / sqrt(256)
        if (lane == 0) g_logits[e] = p;
        m = fmaxf(m, p);
    }

    float acc[8];
#pragma unroll
    for (int r = 0; r < 8; r++) acc[r] = 0.f;
    float ssum = 0.f;
    for (int e = beg; e < end; e++) {
        int src = g_srcs[e];
        float w = __expf(g_logits[e] - m);
        ssum += w;
        const float* vp = &g_v[(size_t)src * DD];
#pragma unroll
        for (int r = 0; r < 8; r++) acc[r] = fmaf(w, vp[r * 32 + lane], acc[r]);
    }

    float inv = (end > beg) ? (1.f / ssum) : 0.f;
#pragma unroll
    for (int r = 0; r < 8; r++) {
        float val = acc[r] * inv + g_s[(size_t)gw * DD + r * 32 + lane];
        g_hA[(size_t)gw * DD + r * 32 + lane] = fmaxf(val, 0.f);
    }
}

// -------- SAGE mean aggregation: warp per node ----------
__global__ void mean_kernel(const float* __restrict__ h)
{
    int gw = (blockIdx.x * blockDim.x + threadIdx.x) >> 5;
    int lane = threadIdx.x & 31;
    if (gw >= NN) return;
    int beg = g_rowptr[gw], end = g_rowptr[gw + 1];

    float acc[8];
#pragma unroll
    for (int r = 0; r < 8; r++) acc[r] = 0.f;
    for (int e = beg; e < end; e++) {
        int src = g_srcs[e];
        const float* hp = &h[(size_t)src * DD];
#pragma unroll
        for (int r = 0; r < 8; r++) acc[r] += hp[r * 32 + lane];
    }
    int deg = end - beg;
    float inv = 1.f / (float)(deg > 0 ? deg : 1);
#pragma unroll
    for (int r = 0; r < 8; r++)
        g_mean[(size_t)gw * DD + r * 32 + lane] = acc[r] * inv;
}

// -------- BN + gated residual + relu epilogue ----------
__global__ void epilogue_kernel(const float* __restrict__ hin, float* __restrict__ hout,
                                const float* __restrict__ gamma, const float* __restrict__ beta,
                                const float* __restrict__ alpha)
{
    int i = blockIdx.x * blockDim.x + threadIdx.x;
    if (i >= NDTOT) return;
    int c = i & 255;
    float al = 1.f / (1.f + __expf(-alpha[0]));
    const float BNS = 0.9999950000374994f;   // 1/sqrt(1+1e-5)
    float zz = fmaf(g_z[i] * BNS, gamma[c], beta[c]);
    float val = al * zz + (1.f - al) * hin[i];
    hout[i] = fmaxf(val, 0.f);
}

// -------- launch ----------
extern "C" void kernel_launch(void* const* d_in, const int* in_sizes, int n_in,
                              void* d_out, int out_size)
{
    const float* x     = (const float*)d_in[0];
    const int*   ei    = (const int*)d_in[1];       // int32! (jax x64 disabled)
    const float* Wq    = (const float*)d_in[2];
    const float* bq    = (const float*)d_in[3];
    const float* Wk    = (const float*)d_in[4];
    const float* bk    = (const float*)d_in[5];
    const float* Wv    = (const float*)d_in[6];
    const float* bv    = (const float*)d_in[7];
    const float* Ws    = (const float*)d_in[8];
    const float* bs    = (const float*)d_in[9];
    const float* Wl    = (const float*)d_in[10];
    const float* bl    = (const float*)d_in[11];
    const float* Wr    = (const float*)d_in[12];
    const float* gamma = (const float*)d_in[13];
    const float* beta  = (const float*)d_in[14];
    const float* alpha = (const float*)d_in[15];
    float*       out   = (float*)d_out;

    float *q, *k, *v, *s, *hA, *hB, *mean, *z;
    cudaGetSymbolAddress((void**)&q,    g_q);
    cudaGetSymbolAddress((void**)&k,    g_k);
    cudaGetSymbolAddress((void**)&v,    g_v);
    cudaGetSymbolAddress((void**)&s,    g_s);
    cudaGetSymbolAddress((void**)&hA,   g_hA);
    cudaGetSymbolAddress((void**)&hB,   g_hB);
    cudaGetSymbolAddress((void**)&mean, g_mean);
    cudaGetSymbolAddress((void**)&z,    g_z);

    dim3 gg((NN + 63) / 64, 4), gb(256);

    // projections
    gemm_bias<<<gg, gb>>>(x, Wq, bq, q, NN, 0);
    gemm_bias<<<gg, gb>>>(x, Wk, bk, k, NN, 0);
    gemm_bias<<<gg, gb>>>(x, Wv, bv, v, NN, 0);
    gemm_bias<<<gg, gb>>>(x, Ws, bs, s, NN, 0);

    // CSR build
    zero_cnt_kernel<<<(NN + 255) / 256, 256>>>();
    hist_kernel<<<(EE + 255) / 256, 256>>>(ei);
    scan_kernel<<<1, 1024>>>();
    scatter_kernel<<<(EE + 255) / 256, 256>>>(ei);

    // TransformerConv
    attn_kernel<<<(NN * 32 + 255) / 256, 256>>>();

    // 3 SAGE layers
    float* hin = hA;
    for (int l = 0; l < 3; l++) {
        mean_kernel<<<(NN * 32 + 255) / 256, 256>>>(hin);
        gemm_bias<<<gg, gb>>>(mean, Wl + (size_t)l * 65536, bl + (size_t)l * 256, z, NN, 0);
        gemm_bias<<<gg, gb>>>(hin,  Wr + (size_t)l * 65536, nullptr,               z, NN, 1);
        float* hout = (l == 2) ? out : ((l == 0) ? hB : hA);
        epilogue_kernel<<<(NDTOT + 255) / 256, 256>>>(hin, hout,
                                                      gamma + (size_t)l * 256,
                                                      beta + (size_t)l * 256, alpha);
        hin = hout;
    }
}